// round 14
// baseline (speedup 1.0000x reference)
#include <cuda_runtime.h>
#include <cuda_bf16.h>
#include <stdint.h>

// Problem constants (reference: N=2048, NUM_COLORS=16, x in [0,16))
#define NN     2048
#define NSH    11            // log2(NN)
#define NC     16
#define CELLS  (NN*NN)       // 4,194,304
#define GRID   512           // co-resident grid (148 SMs x 4 blocks >= 512)
#define CHUNK  (CELLS/GRID)  // 8192 cells per block

// dtype modes
#define MODE_I64  0
#define MODE_I32  1
#define MODE_F32  2
#define MODE_F64  3
#define MODE_BF16 4

// ---------------- scratch (static __device__ arrays; no allocs) ----------------
static __device__ unsigned char      g_x8[CELLS];                 // 4 MB
static __device__ int                g_rowhist[NN*NC];
static __device__ int                g_colhist[NN*NC];
static __device__ unsigned long long g_hash[2*NN];
static __device__ int                g_rclass[NN];
static __device__ int                g_cclass[NN];
static __device__ unsigned int       g_table[NC*CELLS];           // 256 MB (slow path only)
static __device__ int                g_scan[CELLS];
static __device__ int                g_bsums[GRID];
static __device__ unsigned int       g_sync[8];                   // monotonic barrier counters
static __device__ unsigned int       g_ccnt[8];                   // monotonic colhist group counters
static __device__ int                g_fast;

// ---------------- grid barrier: monotonic, replay-safe, fenced ----------------
__device__ __forceinline__ void gsync(int id) {
    __syncthreads();
    if (threadIdx.x == 0) {
        __threadfence();
        unsigned old = atomicAdd(&g_sync[id], 1u);
        unsigned target = old - (old % GRID) + GRID;
        while (*(volatile unsigned*)&g_sync[id] < target) { __nanosleep(64); }
        __threadfence();
    }
    __syncthreads();
}

// ---------------- helpers ----------------
__device__ __forceinline__ int hw_ok(unsigned h) {
    return h == 0u || (h >= 0x3F80u && h <= 0x4170u);
}
__device__ int detect_mode(const unsigned* __restrict__ x, int t, int* bad) {
    if (t < 5) bad[t] = 0;
    __syncthreads();
    unsigned w0 = x[2*t], w1 = x[2*t+1];
    if (!(w1 == 0u && w0 < 16u))                         bad[MODE_I64] = 1;
    if (!(w0 < 16u && w1 < 16u))                         bad[MODE_I32] = 1;
    int f0 = (w0 == 0u) || (((w0 & 0xFFFFu) == 0u) && hw_ok(w0 >> 16));
    int f1 = (w1 == 0u) || (((w1 & 0xFFFFu) == 0u) && hw_ok(w1 >> 16));
    if (!(f0 && f1))                                     bad[MODE_F32] = 1;
    if (!(w0 == 0u && (w1 == 0u || (w1 >= 0x3FF00000u && w1 <= 0x402E0000u))))
                                                         bad[MODE_F64] = 1;
    if (!(hw_ok(w0 & 0xFFFFu) && hw_ok(w0 >> 16) &&
          hw_ok(w1 & 0xFFFFu) && hw_ok(w1 >> 16)))       bad[MODE_BF16] = 1;
    __syncthreads();
    if      (!bad[MODE_I64])  return MODE_I64;
    else if (!bad[MODE_I32])  return MODE_I32;
    else if (!bad[MODE_F64])  return MODE_F64;
    else if (!bad[MODE_F32])  return MODE_F32;
    else if (!bad[MODE_BF16]) return MODE_BF16;
    return MODE_I32;
}
__device__ __forceinline__ unsigned long long fnv16_sm(const int* h) {
    unsigned long long hv = 1469598103934665603ULL;
#pragma unroll
    for (int c = 0; c < NC; c++) { hv ^= (unsigned long long)(unsigned)h[c]; hv *= 1099511628211ULL; }
    return hv;
}
__device__ __forceinline__ unsigned long long fnv16_cg(const int* h) {
    unsigned long long hv = 1469598103934665603ULL;
#pragma unroll
    for (int c = 0; c < NC; c++) { hv ^= (unsigned long long)(unsigned)__ldcg(h + c); hv *= 1099511628211ULL; }
    return hv;
}
__device__ __forceinline__ unsigned cell_key(int p) {
    int i = p >> NSH, j = p & (NN-1);
    return ((unsigned)g_x8[p] << 22) | ((unsigned)__ldcg(&g_rclass[i]) << NSH)
                                     | (unsigned)__ldcg(&g_cclass[j]);
}

// ---------------- the whole pipeline in ONE kernel ----------------
__global__ void __launch_bounds__(256, 4) k_all(const void* __restrict__ xv,
                                                float* __restrict__ out) {
    __shared__ int bad[5];
    __shared__ int wb[8*NC];
    __shared__ int rh[NC];
    __shared__ unsigned char sb[NC*256];
    __shared__ int red[256];
    __shared__ int ws[8], wo[8];
    __shared__ int fin;

    int t = threadIdx.x, b = blockIdx.x;
    int m = detect_mode((const unsigned*)xv, t, bad);
    int gid = b*256 + t;

    // ---- phase A: init glue + decode 4 rows + row hists + row hashes ----
    if (gid == 0) g_fast = 1;
    if (gid < NN*NC) g_colhist[gid] = 0;

    for (int rr = 0; rr < 4; rr++) {
        int row = b*4 + rr;
        if (t < 8*NC) wb[t] = 0;
        __syncthreads();
        int base = row*NN + t*8;
        unsigned v[8];
        if (m == MODE_I32) {
            const int4* p = (const int4*)((const int*)xv + base);
            int4 a = p[0], bb = p[1];
            v[0]=(unsigned)a.x&0xFu;  v[1]=(unsigned)a.y&0xFu;  v[2]=(unsigned)a.z&0xFu;  v[3]=(unsigned)a.w&0xFu;
            v[4]=(unsigned)bb.x&0xFu; v[5]=(unsigned)bb.y&0xFu; v[6]=(unsigned)bb.z&0xFu; v[7]=(unsigned)bb.w&0xFu;
        } else if (m == MODE_F32) {
            const float4* p = (const float4*)((const float*)xv + base);
            float4 a = p[0], bb = p[1];
            v[0]=(unsigned)(int)a.x&0xFu;  v[1]=(unsigned)(int)a.y&0xFu;  v[2]=(unsigned)(int)a.z&0xFu;  v[3]=(unsigned)(int)a.w&0xFu;
            v[4]=(unsigned)(int)bb.x&0xFu; v[5]=(unsigned)(int)bb.y&0xFu; v[6]=(unsigned)(int)bb.z&0xFu; v[7]=(unsigned)(int)bb.w&0xFu;
        } else if (m == MODE_I64) {
            const unsigned* p = (const unsigned*)xv;
#pragma unroll
            for (int e = 0; e < 8; e++) v[e] = p[2*(base+e)] & 0xFu;
        } else if (m == MODE_F64) {
            const double* p = (const double*)xv;
#pragma unroll
            for (int e = 0; e < 8; e++) v[e] = (unsigned)(int)p[base+e] & 0xFu;
        } else { // BF16
            const unsigned short* p = (const unsigned short*)xv;
#pragma unroll
            for (int e = 0; e < 8; e++)
                v[e] = (unsigned)(int)__uint_as_float((unsigned)p[base+e] << 16) & 0xFu;
        }
        unsigned long long w = 0;
#pragma unroll
        for (int e = 0; e < 8; e++) w |= ((unsigned long long)v[e]) << (8*e);
        ((unsigned long long*)g_x8)[base >> 3] = w;
        int wp = (t >> 5) * NC;
#pragma unroll
        for (int e = 0; e < 8; e++) atomicAdd(&wb[wp + (int)v[e]], 1);
        __syncthreads();
        if (t < NC) {
            int s = 0;
#pragma unroll
            for (int k = 0; k < 8; k++) s += wb[k*NC + t];
            g_rowhist[row*NC + t] = s;
            rh[t] = s;
        }
        __syncthreads();
        if (t == 0) g_hash[row] = fnv16_sm(rh);
    }
    gsync(0);

    // ---- phase B: column hists (blocks 0..255) + per-group hash finisher ----
    if (b < 256) {
        int g  = b & 7;            // column group (256 cols)
        int ch = b >> 3;           // row chunk (64 rows), 32 chunks per group
#pragma unroll
        for (int c = 0; c < NC; c++) sb[c*256 + t] = 0;
        __syncthreads();
        int j  = g*256 + t;
        int r0 = ch*64;
        for (int r = r0; r < r0 + 64; r++) {
            int v = g_x8[r*NN + j];
            sb[v*256 + t]++;
        }
#pragma unroll
        for (int c = 0; c < NC; c++) {
            int cnt = sb[c*256 + t];
            if (cnt) atomicAdd(&g_colhist[j*NC + c], cnt);
        }
        __threadfence();
        __syncthreads();
        if (t == 0) {
            unsigned old = atomicAdd(&g_ccnt[g], 1u);
            fin = ((old % 32u) == 31u);
        }
        __syncthreads();
        if (fin) {
            __threadfence();
            g_hash[NN + j] = fnv16_cg(&g_colhist[j*NC]);
        }
    }
    gsync(1);

    // ---- phase C: classes (8 units per block) + fast-path check ----
    for (int u = 0; u < 8; u++) {
        int unit = b*8 + u;
        int i = unit & (NN-1), isCol = unit >> 11;
        const unsigned long long* H = g_hash + isCol*NN;
        const int* hist = isCol ? g_colhist : g_rowhist;
        unsigned long long hi = __ldcg(&H[i]);
        int best = i;
        for (int j = t; j < i; j += 256) {
            if (__ldcg(&H[j]) == hi) {
                bool eq = true;
#pragma unroll
                for (int c = 0; c < NC; c++)
                    eq = eq && (__ldcg(&hist[j*NC + c]) == __ldcg(&hist[i*NC + c]));
                if (eq && j < best) best = j;
            }
        }
        red[t] = best;
        __syncthreads();
        for (int s = 128; s; s >>= 1) {
            if (t < s) red[t] = min(red[t], red[t+s]);
            __syncthreads();
        }
        if (t == 0) {
            (isCol ? g_cclass : g_rclass)[i] = red[0];
            if (red[0] != i) g_fast = 0;
        }
        __syncthreads();
    }
    gsync(2);

    // ---- phase D: output ----
    int fast = *(volatile int*)&g_fast;
    if (fast) {
        // out[p] = p — every key unique, first occurrence everywhere.
#pragma unroll
        for (int k = 0; k < 8; k++) {
            int p = b*CHUNK + k*1024 + t*4;
            *(float4*)(out + p) = make_float4((float)p, (float)(p+1), (float)(p+2), (float)(p+3));
        }
        return;
    }

    // ---- slow path (exact, never expected; co-resident barriers) ----
    int cbase = b*CHUNK;
    for (int p = cbase + t; p < cbase + CHUNK; p += 256)
        g_table[cell_key(p)] = 0xFFFFFFFFu;
    gsync(3);
    for (int p = cbase + t; p < cbase + CHUNK; p += 256)
        atomicMin(&g_table[cell_key(p)], (unsigned)p);
    gsync(4);
    {
        int carry = 0;
        for (int sub = 0; sub < 2; sub++) {
            int base = cbase + sub*4096 + t*16;
            int f[16], s = 0;
#pragma unroll
            for (int e = 0; e < 16; e++) {
                int p = base + e;
                f[e] = (__ldcg(&g_table[cell_key(p)]) == (unsigned)p);
                s += f[e];
            }
            int lane = t & 31, warp = t >> 5;
            int v = s;
#pragma unroll
            for (int o = 1; o < 32; o <<= 1) {
                int nv = __shfl_up_sync(0xffffffffu, v, o);
                if (lane >= o) v += nv;
            }
            if (lane == 31) ws[warp] = v;
            __syncthreads();
            if (t < 8) {
                int w = ws[t];
#pragma unroll
                for (int o = 1; o < 8; o <<= 1) {
                    int nv = __shfl_up_sync(0xffu, w, o);
                    if (t >= o) w += nv;
                }
                wo[t] = w;
            }
            __syncthreads();
            int ex = (v - s) + (warp ? wo[warp-1] : 0);
            int run = carry + ex;
#pragma unroll
            for (int e = 0; e < 16; e++) { g_scan[base + e] = run; run += f[e]; }
            carry += wo[7];
            __syncthreads();
        }
        if (t == 0) g_bsums[b] = carry;
    }
    gsync(5);
    if (b == 0 && t == 0) {
        int acc = 0;
        for (int q = 0; q < GRID; q++) {
            int s = g_bsums[q];
            g_bsums[q] = acc;
            acc += s;
        }
    }
    gsync(6);
    for (int p = cbase + t; p < cbase + CHUNK; p += 256) {
        unsigned q = __ldcg(&g_table[cell_key(p)]);
        out[p] = (float)(__ldcg(&g_scan[q]) + __ldcg(&g_bsums[q >> 13]));
    }
}

// ---------------- launch (1 kernel) ----------------
extern "C" void kernel_launch(void* const* d_in, const int* in_sizes, int n_in,
                              void* d_out, int out_size) {
    const void* x = d_in[0];
    (void)in_sizes; (void)n_in; (void)out_size;
    k_all<<<GRID, 256>>>(x, (float*)d_out);
}